// round 16
// baseline (speedup 1.0000x reference)
#include <cuda_runtime.h>
#include <cuda_bf16.h>
#include <cstdint>

// Problem constants
#define Bc 2
#define Hc 8
#define Nc 2048
#define Pc 64
#define Mc 4
#define Dc 256
#define NX 4096

#define TH 256
#define GRID 456                // 3 CTAs x 152 SMs
#define NU 4096                 // u = bh*256 + nb*8 + jb (jb innermost)
#define LOG2E 1.4426950408889634f

// g_Wf: W fragments, per tile (bh*8+jb): [k(4)][c(128)][q(4)][h(2)] bf16x2,
//   pre-scaled by log2e; c = wc*32 + m*8 + dlow, d = jb*32 + wc*8 + dlow.
// g_Xf: X A-fragments per (bh, nb, wn): [i(4)][k(4)][lane(32)][4 words].
// g_Sf: per (jb, wc, lane): [ s[m] for d=2q ; s[m] for d=2q+1 ] f32.
__device__ uint32_t g_Wf[16 * 8 * 4096];        // 2 MB
__device__ uint32_t g_Xf[16 * 32 * 2 * 2048];   // 8 MB
__device__ float    g_Sf[8 * 4 * 32 * 8];       // 32 KB

__device__ __forceinline__ uint32_t pack_bf16x2(float lo, float hi) {
    uint32_t r;
    asm("cvt.rn.bf16x2.f32 %0, %1, %2;" : "=r"(r) : "f"(hi), "f"(lo));
    return r;
}
__device__ __forceinline__ float ex2f(float x) {
    float r;
    asm("ex2.approx.ftz.f32 %0, %1;" : "=f"(r) : "f"(x));
    return r;
}

// ---- Prep (unchanged from round 15) ----
__global__ void __launch_bounds__(TH) prep_kernel(
    const float* __restrict__ Q, const float* __restrict__ Km,
    const int* __restrict__ sk, const float* __restrict__ sgn)
{
    const int t = blockIdx.x * TH + threadIdx.x;
    if (t < 65536) {
        const int tile = t >> 9;
        const int rem = t & 511;
        const int c = rem >> 2, k = rem & 3;
        const int bh = tile >> 3, jb = tile & 7;
        const int m = (c >> 3) & 3;
        const int d = jb * 32 + (c >> 5) * 8 + (c & 7);
        const int s = sk[((bh >> 3) * Mc + m) * Dc + d];
        const float* src = (s < Nc)
            ? (Q  + (size_t)bh * Nc * Pc + (size_t)s * Pc)
            : (Km + (size_t)bh * Nc * Pc + (size_t)(s - Nc) * Pc);
        src += k * 16;
        float4 f0 = *(const float4*)(src);
        float4 f1 = *(const float4*)(src + 4);
        float4 f2 = *(const float4*)(src + 8);
        float4 f3 = *(const float4*)(src + 12);
        uint32_t* dst = g_Wf + (size_t)tile * 4096 + k * 1024 + c * 8;
        *(uint4*)dst = make_uint4(
            pack_bf16x2(f0.x * LOG2E, f0.y * LOG2E),
            pack_bf16x2(f2.x * LOG2E, f2.y * LOG2E),
            pack_bf16x2(f0.z * LOG2E, f0.w * LOG2E),
            pack_bf16x2(f2.z * LOG2E, f2.w * LOG2E));
        *(uint4*)(dst + 4) = make_uint4(
            pack_bf16x2(f1.x * LOG2E, f1.y * LOG2E),
            pack_bf16x2(f3.x * LOG2E, f3.y * LOG2E),
            pack_bf16x2(f1.z * LOG2E, f1.w * LOG2E),
            pack_bf16x2(f3.z * LOG2E, f3.w * LOG2E));
    } else if (t < 66560) {
        const int tx = t - 65536;
        const int lane = tx & 31, wc = (tx >> 5) & 3, jb = tx >> 7;
        const int q = lane & 3;
        const int dA = jb * 32 + wc * 8 + 2 * q;
        float* dst = g_Sf + (size_t)tx * 8;
        #pragma unroll
        for (int m = 0; m < 4; m++) {
            dst[m]     = sgn[m * Dc + dA];
            dst[m + 4] = sgn[m * Dc + dA + 1];
        }
    } else {
        const int tx = t - 66560;
        const int lane = tx & 31;
        const int k = (tx >> 5) & 3;
        const int i = (tx >> 7) & 3;
        const int wn = (tx >> 9) & 1;
        const int nb = (tx >> 10) & 31;
        const int bh = tx >> 15;
        const int g = lane >> 2, q = lane & 3;
        const int row0 = nb * 128 + wn * 64 + i * 16 + g;
        const int kc = k * 16 + 2 * q;
        auto ldx = [&](int n, int col) -> uint32_t {
            const float* src = (n < Nc)
                ? (Q  + (size_t)bh * Nc * Pc + (size_t)n * Pc + col)
                : (Km + (size_t)bh * Nc * Pc + (size_t)(n - Nc) * Pc + col);
            float2 v = *(const float2*)src;
            return pack_bf16x2(v.x, v.y);
        };
        *(uint4*)(g_Xf + (size_t)tx * 4) = make_uint4(
            ldx(row0,     kc), ldx(row0 + 8, kc),
            ldx(row0,     kc + 8), ldx(row0 + 8, kc + 8));
    }
}

__global__ void __launch_bounds__(TH, 3) sketch_attn_occ(
    float* __restrict__ out)
{
    const int tid = threadIdx.x;
    const int u0 = (NU * blockIdx.x) / GRID;
    const int u1 = (NU * (blockIdx.x + 1)) / GRID;

    const int lane = tid & 31, warp = tid >> 5;
    const int wn = warp & 1, wc = warp >> 1;
    const int na = wn * 64, ca = wc * 32;
    const int g = lane >> 2, q = lane & 3;

    for (int u = u0; u < u1; u++) {
        const int bh = u >> 8;
        const int nb = (u >> 3) & 31;
        const int jb = u & 7;

        // B fragments: 16 coalesced LDG.64 (L1/L2-hot). jj == m.
        const uint32_t* wf = g_Wf + (size_t)((bh << 3) + jb) * 4096
                           + ca * 8 + lane * 2;
        uint2 bb[4][4];   // [k][m]
        #pragma unroll
        for (int k = 0; k < 4; k++)
            #pragma unroll
            for (int m = 0; m < 4; m++)
                bb[k][m] = *(const uint2*)(wf + k * 1024 + m * 64);

        // Sign coefficients.
        const float4* sf = (const float4*)(g_Sf
            + ((size_t)(jb * 4 + wc) * 32 + lane) * 8);
        float4 sLv = sf[0], sHv = sf[1];
        const float sL[4] = {sLv.x, sLv.y, sLv.z, sLv.w};
        const float sH[4] = {sHv.x, sHv.y, sHv.z, sHv.w};

        const uint4* xf = (const uint4*)(g_Xf
            + ((size_t)((bh * 32 + nb) * 2 + wn)) * 2048) + lane;
        float* obase = out + (((size_t)bh * NX + nb * 128 + na + g) * Dc)
                     + jb * 32 + wc * 8 + 2 * q;

        #pragma unroll
        for (int i = 0; i < 4; i++) {
            // A fragments for this 16-row block: 4 LDG.128, L1-hot
            // (slice reused across the 8 jb-units of this (bh, nb)).
            uint4 a[4];
            #pragma unroll
            for (int k = 0; k < 4; k++)
                a[k] = xf[(i * 4 + k) * 32];

            float v00 = 0.f, v01 = 0.f, v10 = 0.f, v11 = 0.f;
            // m-fused: 4-MMA chain for m, then immediately its exps.
            // acc lives only inside the m iteration (4 regs).
            #pragma unroll
            for (int m = 0; m < 4; m++) {
                float a0 = 0.f, a1 = 0.f, a2 = 0.f, a3 = 0.f;
                #pragma unroll
                for (int k = 0; k < 4; k++)
                    asm volatile(
                        "mma.sync.aligned.m16n8k16.row.col.f32.bf16.bf16.f32 "
                        "{%0,%1,%2,%3}, {%4,%5,%6,%7}, {%8,%9}, {%0,%1,%2,%3};\n"
                        : "+f"(a0), "+f"(a1), "+f"(a2), "+f"(a3)
                        : "r"(a[k].x), "r"(a[k].y), "r"(a[k].z), "r"(a[k].w),
                          "r"(bb[k][m].x), "r"(bb[k][m].y));
                v00 += sL[m] * ex2f(a0);   // row g,   d = 2q
                v01 += sH[m] * ex2f(a1);   // row g,   d = 2q+1
                v10 += sL[m] * ex2f(a2);   // row g+8, d = 2q
                v11 += sH[m] * ex2f(a3);   // row g+8, d = 2q+1
            }
            float* orow = obase + (size_t)i * 16 * Dc;
            *(float2*)orow            = make_float2(v00, v01);
            *(float2*)(orow + 8 * Dc) = make_float2(v10, v11);
        }
    }
}

extern "C" void kernel_launch(void* const* d_in, const int* in_sizes, int n_in,
                              void* d_out, int out_size)
{
    const float* Q  = (const float*)d_in[0];
    const float* K  = (const float*)d_in[1];
    const int*   sk = (const int*)d_in[2];
    const float* sg = (const float*)d_in[3];
    float* out = (float*)d_out;

    prep_kernel<<<2308, TH>>>(Q, K, sk, sg);
    sketch_attn_occ<<<GRID, TH>>>(out);
}

// round 17
// speedup vs baseline: 1.0616x; 1.0616x over previous
#include <cuda_runtime.h>
#include <cuda_bf16.h>
#include <cstdint>

// Problem constants
#define Bc 2
#define Hc 8
#define Nc 2048
#define Pc 64
#define Mc 4
#define Dc 256
#define NX 4096

#define TH 256
#define GRID 304                // 2 CTAs x 152 SMs
#define NU 4096                 // u = bh*256 + nb*8 + jb (jb innermost)
#define LOG2E 1.4426950408889634f

// g_Wf: W fragments, per tile (bh*8+jb): [k(4)][c(128)][q(4)][h(2)] bf16x2,
//   pre-scaled by log2e; c = wc*32 + m*8 + dlow, d = jb*32 + wc*8 + dlow
//   -> warp-tile jj == m (thread-local m-reduction).
// g_Xf: X A-fragments per (bh, nb, wn): [i(4)][k(4)][lane(32)][4 words].
// g_Sf: per (jb, wc, lane): [ s[m] for d=2q ; s[m] for d=2q+1 ] f32.
__device__ uint32_t g_Wf[16 * 8 * 4096];        // 2 MB
__device__ uint32_t g_Xf[16 * 32 * 2 * 2048];   // 8 MB
__device__ float    g_Sf[8 * 4 * 32 * 8];       // 32 KB

__device__ __forceinline__ uint32_t pack_bf16x2(float lo, float hi) {
    uint32_t r;
    asm("cvt.rn.bf16x2.f32 %0, %1, %2;" : "=r"(r) : "f"(hi), "f"(lo));
    return r;
}
__device__ __forceinline__ float ex2f(float x) {
    float r;
    asm("ex2.approx.ftz.f32 %0, %1;" : "=f"(r) : "f"(x));
    return r;
}

// ---- Prep (unchanged from round 15) ----
__global__ void __launch_bounds__(TH) prep_kernel(
    const float* __restrict__ Q, const float* __restrict__ Km,
    const int* __restrict__ sk, const float* __restrict__ sgn)
{
    const int t = blockIdx.x * TH + threadIdx.x;
    if (t < 65536) {
        const int tile = t >> 9;
        const int rem = t & 511;
        const int c = rem >> 2, k = rem & 3;
        const int bh = tile >> 3, jb = tile & 7;
        const int m = (c >> 3) & 3;
        const int d = jb * 32 + (c >> 5) * 8 + (c & 7);
        const int s = sk[((bh >> 3) * Mc + m) * Dc + d];
        const float* src = (s < Nc)
            ? (Q  + (size_t)bh * Nc * Pc + (size_t)s * Pc)
            : (Km + (size_t)bh * Nc * Pc + (size_t)(s - Nc) * Pc);
        src += k * 16;
        float4 f0 = *(const float4*)(src);
        float4 f1 = *(const float4*)(src + 4);
        float4 f2 = *(const float4*)(src + 8);
        float4 f3 = *(const float4*)(src + 12);
        uint32_t* dst = g_Wf + (size_t)tile * 4096 + k * 1024 + c * 8;
        *(uint4*)dst = make_uint4(
            pack_bf16x2(f0.x * LOG2E, f0.y * LOG2E),
            pack_bf16x2(f2.x * LOG2E, f2.y * LOG2E),
            pack_bf16x2(f0.z * LOG2E, f0.w * LOG2E),
            pack_bf16x2(f2.z * LOG2E, f2.w * LOG2E));
        *(uint4*)(dst + 4) = make_uint4(
            pack_bf16x2(f1.x * LOG2E, f1.y * LOG2E),
            pack_bf16x2(f3.x * LOG2E, f3.y * LOG2E),
            pack_bf16x2(f1.z * LOG2E, f1.w * LOG2E),
            pack_bf16x2(f3.z * LOG2E, f3.w * LOG2E));
    } else if (t < 66560) {
        const int tx = t - 65536;
        const int lane = tx & 31, wc = (tx >> 5) & 3, jb = tx >> 7;
        const int q = lane & 3;
        const int dA = jb * 32 + wc * 8 + 2 * q;
        float* dst = g_Sf + (size_t)tx * 8;
        #pragma unroll
        for (int m = 0; m < 4; m++) {
            dst[m]     = sgn[m * Dc + dA];
            dst[m + 4] = sgn[m * Dc + dA + 1];
        }
    } else {
        const int tx = t - 66560;
        const int lane = tx & 31;
        const int k = (tx >> 5) & 3;
        const int i = (tx >> 7) & 3;
        const int wn = (tx >> 9) & 1;
        const int nb = (tx >> 10) & 31;
        const int bh = tx >> 15;
        const int g = lane >> 2, q = lane & 3;
        const int row0 = nb * 128 + wn * 64 + i * 16 + g;
        const int kc = k * 16 + 2 * q;
        auto ldx = [&](int n, int col) -> uint32_t {
            const float* src = (n < Nc)
                ? (Q  + (size_t)bh * Nc * Pc + (size_t)n * Pc + col)
                : (Km + (size_t)bh * Nc * Pc + (size_t)(n - Nc) * Pc + col);
            float2 v = *(const float2*)src;
            return pack_bf16x2(v.x, v.y);
        };
        *(uint4*)(g_Xf + (size_t)tx * 4) = make_uint4(
            ldx(row0,     kc), ldx(row0 + 8, kc),
            ldx(row0,     kc + 8), ldx(row0 + 8, kc + 8));
    }
}

__global__ void __launch_bounds__(TH, 2) sketch_attn_pairfuse(
    float* __restrict__ out)
{
    const int tid = threadIdx.x;
    const int u0 = (NU * blockIdx.x) / GRID;
    const int u1 = (NU * (blockIdx.x + 1)) / GRID;

    const int lane = tid & 31, warp = tid >> 5;
    const int wn = warp & 1, wc = warp >> 1;
    const int na = wn * 64, ca = wc * 32;
    const int g = lane >> 2, q = lane & 3;

    uint4 A[4][4];          // register-resident A fragments (64 regs)
    int curGroup = -1;

    for (int u = u0; u < u1; u++) {
        const int bh = u >> 8;
        const int nb = (u >> 3) & 31;
        const int jb = u & 7;
        const int grp = u >> 3;

        if (grp != curGroup) {
            const uint4* xf = (const uint4*)(g_Xf
                + ((size_t)((bh * 32 + nb) * 2 + wn)) * 2048) + lane;
            #pragma unroll
            for (int i = 0; i < 4; i++)
                #pragma unroll
                for (int k = 0; k < 4; k++)
                    A[i][k] = xf[(i * 4 + k) * 32];
            curGroup = grp;
        }

        // B fragments: 16 coalesced LDG.64 (L1/L2-hot). jj == m.
        const uint32_t* wf = g_Wf + (size_t)((bh << 3) + jb) * 4096
                           + ca * 8 + lane * 2;
        uint2 bb[4][4];   // [k][m]
        #pragma unroll
        for (int k = 0; k < 4; k++)
            #pragma unroll
            for (int m = 0; m < 4; m++)
                bb[k][m] = *(const uint2*)(wf + k * 1024 + m * 64);

        // Sign coefficients.
        const float4* sf = (const float4*)(g_Sf
            + ((size_t)(jb * 4 + wc) * 32 + lane) * 8);
        float4 sLv = sf[0], sHv = sf[1];
        const float sL[4] = {sLv.x, sLv.y, sLv.z, sLv.w};
        const float sH[4] = {sHv.x, sHv.y, sHv.z, sHv.w};

        float* obase = out + (((size_t)bh * NX + nb * 128 + na + g) * Dc)
                     + jb * 32 + wc * 8 + 2 * q;

        // i-major, m-PAIR fused: two independent 4-MMA chains (tensor ILP=2),
        // then that pair's 8 ex2 -> MUFU overlaps the next pair's MMAs.
        #pragma unroll
        for (int i = 0; i < 4; i++) {
            float v00 = 0.f, v01 = 0.f, v10 = 0.f, v11 = 0.f;
            #pragma unroll
            for (int mp = 0; mp < 4; mp += 2) {
                float p0[4] = {0.f, 0.f, 0.f, 0.f};
                float p1[4] = {0.f, 0.f, 0.f, 0.f};
                #pragma unroll
                for (int k = 0; k < 4; k++) {
                    asm volatile(
                        "mma.sync.aligned.m16n8k16.row.col.f32.bf16.bf16.f32 "
                        "{%0,%1,%2,%3}, {%4,%5,%6,%7}, {%8,%9}, {%0,%1,%2,%3};\n"
                        : "+f"(p0[0]), "+f"(p0[1]), "+f"(p0[2]), "+f"(p0[3])
                        : "r"(A[i][k].x), "r"(A[i][k].y),
                          "r"(A[i][k].z), "r"(A[i][k].w),
                          "r"(bb[k][mp].x), "r"(bb[k][mp].y));
                    asm volatile(
                        "mma.sync.aligned.m16n8k16.row.col.f32.bf16.bf16.f32 "
                        "{%0,%1,%2,%3}, {%4,%5,%6,%7}, {%8,%9}, {%0,%1,%2,%3};\n"
                        : "+f"(p1[0]), "+f"(p1[1]), "+f"(p1[2]), "+f"(p1[3])
                        : "r"(A[i][k].x), "r"(A[i][k].y),
                          "r"(A[i][k].z), "r"(A[i][k].w),
                          "r"(bb[k][mp + 1].x), "r"(bb[k][mp + 1].y));
                }
                // Pair epilogue (order: m ascending -> same sum order as before).
                v00 += sL[mp]     * ex2f(p0[0]);
                v01 += sH[mp]     * ex2f(p0[1]);
                v10 += sL[mp]     * ex2f(p0[2]);
                v11 += sH[mp]     * ex2f(p0[3]);
                v00 += sL[mp + 1] * ex2f(p1[0]);
                v01 += sH[mp + 1] * ex2f(p1[1]);
                v10 += sL[mp + 1] * ex2f(p1[2]);
                v11 += sH[mp + 1] * ex2f(p1[3]);
            }
            float* orow = obase + (size_t)i * 16 * Dc;
            *(float2*)orow            = make_float2(v00, v01);   // row g
            *(float2*)(orow + 8 * Dc) = make_float2(v10, v11);   // row g+8
        }
    }
}

extern "C" void kernel_launch(void* const* d_in, const int* in_sizes, int n_in,
                              void* d_out, int out_size)
{
    const float* Q  = (const float*)d_in[0];
    const float* K  = (const float*)d_in[1];
    const int*   sk = (const int*)d_in[2];
    const float* sg = (const float*)d_in[3];
    float* out = (float*)d_out;

    prep_kernel<<<2308, TH>>>(Q, K, sk, sg);
    sketch_attn_pairfuse<<<GRID, TH>>>(out);
}